// round 16
// baseline (speedup 1.0000x reference)
#include <cuda_runtime.h>

// ---------------------------------------------------------------------------
// RandomProjectionQuantizer
//   h[t,:] = hidden[t,0:320] @ P[320,16]   (L2-normalize skipped: argmax is
//                                           invariant to positive row scale)
//   out[t] = (float)argmax_k <h[t], CB[k]> first-index ties; float32 output
//
// proj:   8 threads/token, TWO tokens per thread: every P LDS.128 is shared
//         across both tokens (LDS/token halved) and 20 LDG.128 are in
//         flight (MLP 2x R15). Interleaved float4 ownership (nL=4 lines per
//         warp load). Octet butterfly; lanes q<4 store token A, q>=4 token B.
// argmax: code-PAIR-packed f32x2, TPT=2, tournament compare. NEW:
//         __launch_bounds__(128, 7) -> 7 CTAs/SM so all 1008 CTAs fit in a
//         SINGLE wave (R15 ran ~1.7 waves with a 70%-full tail).
// ---------------------------------------------------------------------------

#define IN_DIM   320
#define E        16
#define CHUNK    512                 // codes per argmax CTA (y-dim)
#define NPAIR    (CHUNK / 2)         // 256 pairs, 32 KB packed smem
#define THREADS  128
#define TPT      2                   // tokens per thread (argmax)
#define TOKB     (THREADS * TPT)     // 256 tokens per argmax CTA
#define TOKENS_MAX 16000

// proj config: 8 threads per token, 2 tokens per thread
#define PQ       8                   // threads cooperating per token
#define PDIMS    (IN_DIM / PQ)       // 40 dims per thread
#define PTHREADS 128
#define PTOK     (PTHREADS / PQ)     // 16 token-slots per CTA pass
#define PTOKB    (PTOK * 2)          // 32 tokens per CTA (A + B)
#define SECT_F   (PDIMS * E + 4)     // 644 floats: +4 pad = 4-bank skew
#define SECT_V   (SECT_F / 4)        // 161 ulonglong2 per section

__device__ __align__(16) float              g_h[TOKENS_MAX * E];
__device__ __align__(16) unsigned long long g_keys[TOKENS_MAX];

typedef unsigned long long u64;

// ---- packed f32x2 ops -----------------------------------------------------
static __device__ __forceinline__ u64 mul2(u64 a, u64 b) {
    u64 d; asm("mul.rn.f32x2 %0, %1, %2;" : "=l"(d) : "l"(a), "l"(b)); return d;
}
static __device__ __forceinline__ u64 fma2(u64 a, u64 b, u64 c) {
    u64 d; asm("fma.rn.f32x2 %0, %1, %2, %3;" : "=l"(d) : "l"(a), "l"(b), "l"(c)); return d;
}
static __device__ __forceinline__ u64 add2(u64 a, u64 b) {
    u64 d; asm("add.rn.f32x2 %0, %1, %2;" : "=l"(d) : "l"(a), "l"(b)); return d;
}
static __device__ __forceinline__ u64 pack2(float lo, float hi) {
    u64 d; asm("mov.b64 %0, {%1, %2};" : "=l"(d) : "f"(lo), "f"(hi)); return d;
}
static __device__ __forceinline__ void unpack2(float& lo, float& hi, u64 v) {
    asm("mov.b64 {%0, %1}, %2;" : "=f"(lo), "=f"(hi) : "l"(v));
}

// ---------------------------------------------------------------------------
// Projection (+ fused key init): PQ=8 threads/token, 2 tokens/thread.
// Thread q owns row float4s f = 8j+q (dims 4f..4f+3), j = 0..9, per token.
__global__ __launch_bounds__(PTHREADS)
void rpq_proj(const float* __restrict__ hs,
              const float* __restrict__ P, int ntok) {
    __shared__ __align__(16) float Ps[PQ * SECT_F];   // ~20.1 KB, skewed
    const int tid = threadIdx.x;

    // stage P: global float4 i -> dim d = i>>2, e-quad w = i&3.
    // owner q = (d>>2)&7; local dim dl = ((d>>5)<<2)|(d&3) in 0..39.
    for (int i = tid; i < IN_DIM * E / 4; i += PTHREADS) {
        int d = i >> 2, w = i & 3;
        int q  = (d >> 2) & 7;
        int dl = ((d >> 5) << 2) | (d & 3);
        ((float4*)Ps)[q * (SECT_F / 4) + dl * 4 + w] = ((const float4*)P)[i];
    }
    __syncthreads();

    const int q  = tid & (PQ - 1);
    const int tl = tid >> 3;
    const int tA = blockIdx.x * PTOKB + tl;           // token A
    const int tB = tA + PTOK;                         // token B
    const bool vA = (tA < ntok);
    const bool vB = (tB < ntok);
    if (q == 0) {
        if (vA) g_keys[tA] = 0ull;                    // fused init
        if (vB) g_keys[tB] = 0ull;
    }

    const float4* rowA = (const float4*)(hs + (long long)(vA ? tA : 0) * IN_DIM);
    const float4* rowB = (const float4*)(hs + (long long)(vB ? tB : 0) * IN_DIM);
    const ulonglong2* Psec = (const ulonglong2*)Ps + q * SECT_V;

    // 20 LDG.128 front-batched (2 tokens); each warp load covers 4 lines.
    float4 xA[PDIMS / 4], xB[PDIMS / 4];
#pragma unroll
    for (int j = 0; j < PDIMS / 4; ++j) xA[j] = rowA[8 * j + q];
#pragma unroll
    for (int j = 0; j < PDIMS / 4; ++j) xB[j] = rowB[8 * j + q];

    u64 accA[8], accB[8];
#pragma unroll
    for (int ep = 0; ep < 8; ep++) { accA[ep] = 0ull; accB[ep] = 0ull; }

#pragma unroll
    for (int j = 0; j < PDIMS / 4; ++j) {
        float xsA[4] = {xA[j].x, xA[j].y, xA[j].z, xA[j].w};
        float xsB[4] = {xB[j].x, xB[j].y, xB[j].z, xB[j].w};
#pragma unroll
        for (int i = 0; i < 4; ++i) {
            int dl = 4 * j + i;                       // local dim index
            u64 xa = pack2(xsA[i], xsA[i]);
            u64 xb = pack2(xsB[i], xsB[i]);
            ulonglong2 pA = Psec[dl * 4 + 0];         // shared by BOTH tokens
            ulonglong2 pB = Psec[dl * 4 + 1];
            ulonglong2 pC = Psec[dl * 4 + 2];
            ulonglong2 pD = Psec[dl * 4 + 3];
            accA[0] = fma2(xa, pA.x, accA[0]);
            accA[1] = fma2(xa, pA.y, accA[1]);
            accA[2] = fma2(xa, pB.x, accA[2]);
            accA[3] = fma2(xa, pB.y, accA[3]);
            accA[4] = fma2(xa, pC.x, accA[4]);
            accA[5] = fma2(xa, pC.y, accA[5]);
            accA[6] = fma2(xa, pD.x, accA[6]);
            accA[7] = fma2(xa, pD.y, accA[7]);
            accB[0] = fma2(xb, pA.x, accB[0]);
            accB[1] = fma2(xb, pA.y, accB[1]);
            accB[2] = fma2(xb, pB.x, accB[2]);
            accB[3] = fma2(xb, pB.y, accB[3]);
            accB[4] = fma2(xb, pC.x, accB[4]);
            accB[5] = fma2(xb, pC.y, accB[5]);
            accB[6] = fma2(xb, pD.x, accB[6]);
            accB[7] = fma2(xb, pD.y, accB[7]);
        }
    }

    // octet butterfly for both tokens (all 8 lanes end with full sums)
#pragma unroll
    for (int o = 1; o <= 4; o <<= 1) {
#pragma unroll
        for (int ep = 0; ep < 8; ep++) {
            u64 oa = __shfl_xor_sync(0xffffffffu, accA[ep], o);
            accA[ep] = add2(accA[ep], oa);
            u64 ob = __shfl_xor_sync(0xffffffffu, accB[ep], o);
            accB[ep] = add2(accB[ep], ob);
        }
    }

    // lanes q=0..3 store token A's qword q; lanes q=4..7 store token B's q-4
    if (q < 4) {
        if (vA) {
            ulonglong2* outv = (ulonglong2*)(g_h + (long long)tA * E);
            outv[q] = make_ulonglong2(accA[2 * q], accA[2 * q + 1]);
        }
    } else {
        if (vB) {
            int qq = q - 4;
            ulonglong2* outv = (ulonglong2*)(g_h + (long long)tB * E);
            outv[qq] = make_ulonglong2(accB[2 * qq], accB[2 * qq + 1]);
        }
    }
}

// ---------------------------------------------------------------------------
// Argmax: pair-packed f32x2, TPT=2, tournament compare, single-wave
// residency (7 CTAs/SM -> 1036 slots >= 1008 CTAs).
__global__ __launch_bounds__(THREADS, 7)
void rpq_argmax(const float* __restrict__ CB, int ntok, int kcodes) {
    __shared__ __align__(16) u64 cbp[NPAIR * E];     // 32 KB

    const int tid   = threadIdx.x;
    const int kbase = blockIdx.y * CHUNK;

    for (int i = tid; i < NPAIR * 4; i += THREADS) {
        int p = i >> 2, q = i & 3;
        const float4* c0 = (const float4*)(CB + (long long)(kbase + 2 * p) * E) + q;
        const float4* c1 = (const float4*)(CB + (long long)(kbase + 2 * p + 1) * E) + q;
        float4 a = *c0, b = *c1;
        u64* dst = &cbp[p * E + q * 4];
        dst[0] = pack2(a.x, b.x);
        dst[1] = pack2(a.y, b.y);
        dst[2] = pack2(a.z, b.z);
        dst[3] = pack2(a.w, b.w);
    }

    u64  hd[TPT][E];
    int  tok[TPT];
    bool valid[TPT];
#pragma unroll
    for (int i = 0; i < TPT; i++) {
        int t = blockIdx.x * TOKB + tid + i * THREADS;
        tok[i] = t;
        valid[i] = (t < ntok);
        const float4* hv = (const float4*)(g_h + (long long)(valid[i] ? t : 0) * E);
        float4 h0 = hv[0], h1 = hv[1], h2 = hv[2], h3 = hv[3];
        hd[i][0]  = pack2(h0.x, h0.x); hd[i][1]  = pack2(h0.y, h0.y);
        hd[i][2]  = pack2(h0.z, h0.z); hd[i][3]  = pack2(h0.w, h0.w);
        hd[i][4]  = pack2(h1.x, h1.x); hd[i][5]  = pack2(h1.y, h1.y);
        hd[i][6]  = pack2(h1.z, h1.z); hd[i][7]  = pack2(h1.w, h1.w);
        hd[i][8]  = pack2(h2.x, h2.x); hd[i][9]  = pack2(h2.y, h2.y);
        hd[i][10] = pack2(h2.z, h2.z); hd[i][11] = pack2(h2.w, h2.w);
        hd[i][12] = pack2(h3.x, h3.x); hd[i][13] = pack2(h3.y, h3.y);
        hd[i][14] = pack2(h3.z, h3.z); hd[i][15] = pack2(h3.w, h3.w);
    }
    __syncthreads();

    float best[TPT];
    int   bidx[TPT];
#pragma unroll
    for (int i = 0; i < TPT; i++) { best[i] = -3.402823466e38f; bidx[i] = 0; }

    const ulonglong2* pv = (const ulonglong2*)cbp;
    for (int p = 0; p < NPAIR; ++p) {
        ulonglong2 v0 = pv[p * 8 + 0], v1 = pv[p * 8 + 1];
        ulonglong2 v2 = pv[p * 8 + 2], v3 = pv[p * 8 + 3];
        ulonglong2 v4 = pv[p * 8 + 4], v5 = pv[p * 8 + 5];
        ulonglong2 v6 = pv[p * 8 + 6], v7 = pv[p * 8 + 7];
#pragma unroll
        for (int i = 0; i < TPT; i++) {
            u64 a0 = mul2(hd[i][0],  v0.x);
            u64 a1 = mul2(hd[i][1],  v0.y);
            a0 = fma2(hd[i][2],  v1.x, a0);
            a1 = fma2(hd[i][3],  v1.y, a1);
            a0 = fma2(hd[i][4],  v2.x, a0);
            a1 = fma2(hd[i][5],  v2.y, a1);
            a0 = fma2(hd[i][6],  v3.x, a0);
            a1 = fma2(hd[i][7],  v3.y, a1);
            a0 = fma2(hd[i][8],  v4.x, a0);
            a1 = fma2(hd[i][9],  v4.y, a1);
            a0 = fma2(hd[i][10], v5.x, a0);
            a1 = fma2(hd[i][11], v5.y, a1);
            a0 = fma2(hd[i][12], v6.x, a0);
            a1 = fma2(hd[i][13], v6.y, a1);
            a0 = fma2(hd[i][14], v7.x, a0);
            a1 = fma2(hd[i][15], v7.y, a1);
            a0 = add2(a0, a1);               // (score_2p, score_2p+1)
            float slo, shi;
            unpack2(slo, shi, a0);
            float smax = fmaxf(slo, shi);
            int   isel = (slo >= shi) ? (2 * p) : (2 * p + 1);
            if (smax > best[i]) { best[i] = smax; bidx[i] = isel; }
        }
    }

#pragma unroll
    for (int i = 0; i < TPT; i++) {
        if (!valid[i]) continue;
        int gidx = kbase + bidx[i];
        unsigned ub = __float_as_uint(best[i]);
        ub = (ub & 0x80000000u) ? ~ub : (ub | 0x80000000u);  // sortable fp32
        u64 key = ((u64)ub << 32) | (unsigned)(0x7FFFFFFF - gidx);
        atomicMax(&g_keys[tok[i]], key);
    }
}

// ---------------------------------------------------------------------------
__global__ void rpq_finalize(float* __restrict__ out, int ntok, int total) {
    int t = blockIdx.x * blockDim.x + threadIdx.x;
    if (t < ntok)
        out[t] = (float)(0x7FFFFFFF - (int)(g_keys[t] & 0xFFFFFFFFull));
    else if (t < total)
        out[t] = 0.f;
}

// ---------------------------------------------------------------------------
extern "C" void kernel_launch(void* const* d_in, const int* in_sizes, int n_in,
                              void* d_out, int out_size) {
    // Bind by element count: hidden (largest), P (smallest), CB (remaining).
    int ih = 0, ip = 0;
    for (int i = 1; i < n_in; i++) {
        if (in_sizes[i] > in_sizes[ih]) ih = i;
        if (in_sizes[i] < in_sizes[ip]) ip = i;
    }
    int ic = 0;
    for (int i = 0; i < n_in; i++)
        if (i != ih && i != ip) ic = i;

    const float* hs = (const float*)d_in[ih];
    const float* P  = (const float*)d_in[ip];
    const float* CB = (const float*)d_in[ic];
    float* out = (float*)d_out;            // float32 labels (R6-proven)

    int ntok   = in_sizes[ih] / IN_DIM;    // 16000
    int kcodes = in_sizes[ic] / E;         // 8192

    rpq_proj<<<(ntok + PTOKB - 1) / PTOKB, PTHREADS>>>(hs, P, ntok);

    dim3 g2((ntok + TOKB - 1) / TOKB, kcodes / CHUNK);   // (63, 16)
    rpq_argmax<<<g2, THREADS>>>(CB, ntok, kcodes);

    rpq_finalize<<<(out_size + 127) / 128, 128>>>(out, ntok, out_size);
}

// round 17
// speedup vs baseline: 1.0529x; 1.0529x over previous
#include <cuda_runtime.h>

// ---------------------------------------------------------------------------
// RandomProjectionQuantizer
//   h[t,:] = hidden[t,0:320] @ P[320,16]   (L2-normalize skipped: argmax is
//                                           invariant to positive row scale)
//   out[t] = (float)argmax_k <h[t], CB[k]> first-index ties; float32 output
//
// proj:   8 threads/token, TWO tokens per thread (R16, measured 17.3 us):
//         P LDS.128 shared across both tokens, 20 LDG.128 in flight,
//         interleaved float4 ownership (4 lines per warp load).
// argmax: code-PAIR-packed f32x2, TPT=2, tournament compare, DEFAULT
//         occupancy bound (R15, measured ~85 us — the forced 7-CTA/SM
//         variant in R16 spilled and regressed to ~91).
// ---------------------------------------------------------------------------

#define IN_DIM   320
#define E        16
#define CHUNK    512                 // codes per argmax CTA (y-dim)
#define NPAIR    (CHUNK / 2)         // 256 pairs, 32 KB packed smem
#define THREADS  128
#define TPT      2                   // tokens per thread (argmax)
#define TOKB     (THREADS * TPT)     // 256 tokens per argmax CTA
#define TOKENS_MAX 16000

// proj config: 8 threads per token, 2 tokens per thread
#define PQ       8                   // threads cooperating per token
#define PDIMS    (IN_DIM / PQ)       // 40 dims per thread
#define PTHREADS 128
#define PTOK     (PTHREADS / PQ)     // 16 token-slots per CTA pass
#define PTOKB    (PTOK * 2)          // 32 tokens per CTA (A + B)
#define SECT_F   (PDIMS * E + 4)     // 644 floats: +4 pad = 4-bank skew
#define SECT_V   (SECT_F / 4)        // 161 ulonglong2 per section

__device__ __align__(16) float              g_h[TOKENS_MAX * E];
__device__ __align__(16) unsigned long long g_keys[TOKENS_MAX];

typedef unsigned long long u64;

// ---- packed f32x2 ops -----------------------------------------------------
static __device__ __forceinline__ u64 mul2(u64 a, u64 b) {
    u64 d; asm("mul.rn.f32x2 %0, %1, %2;" : "=l"(d) : "l"(a), "l"(b)); return d;
}
static __device__ __forceinline__ u64 fma2(u64 a, u64 b, u64 c) {
    u64 d; asm("fma.rn.f32x2 %0, %1, %2, %3;" : "=l"(d) : "l"(a), "l"(b), "l"(c)); return d;
}
static __device__ __forceinline__ u64 add2(u64 a, u64 b) {
    u64 d; asm("add.rn.f32x2 %0, %1, %2;" : "=l"(d) : "l"(a), "l"(b)); return d;
}
static __device__ __forceinline__ u64 pack2(float lo, float hi) {
    u64 d; asm("mov.b64 %0, {%1, %2};" : "=l"(d) : "f"(lo), "f"(hi)); return d;
}
static __device__ __forceinline__ void unpack2(float& lo, float& hi, u64 v) {
    asm("mov.b64 {%0, %1}, %2;" : "=f"(lo), "=f"(hi) : "l"(v));
}

// ---------------------------------------------------------------------------
// Projection (+ fused key init): PQ=8 threads/token, 2 tokens/thread.
__global__ __launch_bounds__(PTHREADS)
void rpq_proj(const float* __restrict__ hs,
              const float* __restrict__ P, int ntok) {
    __shared__ __align__(16) float Ps[PQ * SECT_F];   // ~20.1 KB, skewed
    const int tid = threadIdx.x;

    // stage P: global float4 i -> dim d = i>>2, e-quad w = i&3.
    // owner q = (d>>2)&7; local dim dl = ((d>>5)<<2)|(d&3) in 0..39.
    for (int i = tid; i < IN_DIM * E / 4; i += PTHREADS) {
        int d = i >> 2, w = i & 3;
        int q  = (d >> 2) & 7;
        int dl = ((d >> 5) << 2) | (d & 3);
        ((float4*)Ps)[q * (SECT_F / 4) + dl * 4 + w] = ((const float4*)P)[i];
    }
    __syncthreads();

    const int q  = tid & (PQ - 1);
    const int tl = tid >> 3;
    const int tA = blockIdx.x * PTOKB + tl;           // token A
    const int tB = tA + PTOK;                         // token B
    const bool vA = (tA < ntok);
    const bool vB = (tB < ntok);
    if (q == 0) {
        if (vA) g_keys[tA] = 0ull;                    // fused init
        if (vB) g_keys[tB] = 0ull;
    }

    const float4* rowA = (const float4*)(hs + (long long)(vA ? tA : 0) * IN_DIM);
    const float4* rowB = (const float4*)(hs + (long long)(vB ? tB : 0) * IN_DIM);
    const ulonglong2* Psec = (const ulonglong2*)Ps + q * SECT_V;

    // 20 LDG.128 front-batched (2 tokens); each warp load covers 4 lines.
    float4 xA[PDIMS / 4], xB[PDIMS / 4];
#pragma unroll
    for (int j = 0; j < PDIMS / 4; ++j) xA[j] = rowA[8 * j + q];
#pragma unroll
    for (int j = 0; j < PDIMS / 4; ++j) xB[j] = rowB[8 * j + q];

    u64 accA[8], accB[8];
#pragma unroll
    for (int ep = 0; ep < 8; ep++) { accA[ep] = 0ull; accB[ep] = 0ull; }

#pragma unroll
    for (int j = 0; j < PDIMS / 4; ++j) {
        float xsA[4] = {xA[j].x, xA[j].y, xA[j].z, xA[j].w};
        float xsB[4] = {xB[j].x, xB[j].y, xB[j].z, xB[j].w};
#pragma unroll
        for (int i = 0; i < 4; ++i) {
            int dl = 4 * j + i;                       // local dim index
            u64 xa = pack2(xsA[i], xsA[i]);
            u64 xb = pack2(xsB[i], xsB[i]);
            ulonglong2 pA = Psec[dl * 4 + 0];         // shared by BOTH tokens
            ulonglong2 pB = Psec[dl * 4 + 1];
            ulonglong2 pC = Psec[dl * 4 + 2];
            ulonglong2 pD = Psec[dl * 4 + 3];
            accA[0] = fma2(xa, pA.x, accA[0]);
            accA[1] = fma2(xa, pA.y, accA[1]);
            accA[2] = fma2(xa, pB.x, accA[2]);
            accA[3] = fma2(xa, pB.y, accA[3]);
            accA[4] = fma2(xa, pC.x, accA[4]);
            accA[5] = fma2(xa, pC.y, accA[5]);
            accA[6] = fma2(xa, pD.x, accA[6]);
            accA[7] = fma2(xa, pD.y, accA[7]);
            accB[0] = fma2(xb, pA.x, accB[0]);
            accB[1] = fma2(xb, pA.y, accB[1]);
            accB[2] = fma2(xb, pB.x, accB[2]);
            accB[3] = fma2(xb, pB.y, accB[3]);
            accB[4] = fma2(xb, pC.x, accB[4]);
            accB[5] = fma2(xb, pC.y, accB[5]);
            accB[6] = fma2(xb, pD.x, accB[6]);
            accB[7] = fma2(xb, pD.y, accB[7]);
        }
    }

    // octet butterfly for both tokens (all 8 lanes end with full sums)
#pragma unroll
    for (int o = 1; o <= 4; o <<= 1) {
#pragma unroll
        for (int ep = 0; ep < 8; ep++) {
            u64 oa = __shfl_xor_sync(0xffffffffu, accA[ep], o);
            accA[ep] = add2(accA[ep], oa);
            u64 ob = __shfl_xor_sync(0xffffffffu, accB[ep], o);
            accB[ep] = add2(accB[ep], ob);
        }
    }

    // lanes q=0..3 store token A's qword q; lanes q=4..7 store token B's q-4
    if (q < 4) {
        if (vA) {
            ulonglong2* outv = (ulonglong2*)(g_h + (long long)tA * E);
            outv[q] = make_ulonglong2(accA[2 * q], accA[2 * q + 1]);
        }
    } else {
        if (vB) {
            int qq = q - 4;
            ulonglong2* outv = (ulonglong2*)(g_h + (long long)tB * E);
            outv[qq] = make_ulonglong2(accB[2 * qq], accB[2 * qq + 1]);
        }
    }
}

// ---------------------------------------------------------------------------
// Argmax: pair-packed f32x2, TPT=2, tournament compare, default occupancy.
__global__ __launch_bounds__(THREADS)
void rpq_argmax(const float* __restrict__ CB, int ntok, int kcodes) {
    __shared__ __align__(16) u64 cbp[NPAIR * E];     // 32 KB

    const int tid   = threadIdx.x;
    const int kbase = blockIdx.y * CHUNK;

    for (int i = tid; i < NPAIR * 4; i += THREADS) {
        int p = i >> 2, q = i & 3;
        const float4* c0 = (const float4*)(CB + (long long)(kbase + 2 * p) * E) + q;
        const float4* c1 = (const float4*)(CB + (long long)(kbase + 2 * p + 1) * E) + q;
        float4 a = *c0, b = *c1;
        u64* dst = &cbp[p * E + q * 4];
        dst[0] = pack2(a.x, b.x);
        dst[1] = pack2(a.y, b.y);
        dst[2] = pack2(a.z, b.z);
        dst[3] = pack2(a.w, b.w);
    }

    u64  hd[TPT][E];
    int  tok[TPT];
    bool valid[TPT];
#pragma unroll
    for (int i = 0; i < TPT; i++) {
        int t = blockIdx.x * TOKB + tid + i * THREADS;
        tok[i] = t;
        valid[i] = (t < ntok);
        const float4* hv = (const float4*)(g_h + (long long)(valid[i] ? t : 0) * E);
        float4 h0 = hv[0], h1 = hv[1], h2 = hv[2], h3 = hv[3];
        hd[i][0]  = pack2(h0.x, h0.x); hd[i][1]  = pack2(h0.y, h0.y);
        hd[i][2]  = pack2(h0.z, h0.z); hd[i][3]  = pack2(h0.w, h0.w);
        hd[i][4]  = pack2(h1.x, h1.x); hd[i][5]  = pack2(h1.y, h1.y);
        hd[i][6]  = pack2(h1.z, h1.z); hd[i][7]  = pack2(h1.w, h1.w);
        hd[i][8]  = pack2(h2.x, h2.x); hd[i][9]  = pack2(h2.y, h2.y);
        hd[i][10] = pack2(h2.z, h2.z); hd[i][11] = pack2(h2.w, h2.w);
        hd[i][12] = pack2(h3.x, h3.x); hd[i][13] = pack2(h3.y, h3.y);
        hd[i][14] = pack2(h3.z, h3.z); hd[i][15] = pack2(h3.w, h3.w);
    }
    __syncthreads();

    float best[TPT];
    int   bidx[TPT];
#pragma unroll
    for (int i = 0; i < TPT; i++) { best[i] = -3.402823466e38f; bidx[i] = 0; }

    const ulonglong2* pv = (const ulonglong2*)cbp;
    for (int p = 0; p < NPAIR; ++p) {
        ulonglong2 v0 = pv[p * 8 + 0], v1 = pv[p * 8 + 1];
        ulonglong2 v2 = pv[p * 8 + 2], v3 = pv[p * 8 + 3];
        ulonglong2 v4 = pv[p * 8 + 4], v5 = pv[p * 8 + 5];
        ulonglong2 v6 = pv[p * 8 + 6], v7 = pv[p * 8 + 7];
#pragma unroll
        for (int i = 0; i < TPT; i++) {
            u64 a0 = mul2(hd[i][0],  v0.x);
            u64 a1 = mul2(hd[i][1],  v0.y);
            a0 = fma2(hd[i][2],  v1.x, a0);
            a1 = fma2(hd[i][3],  v1.y, a1);
            a0 = fma2(hd[i][4],  v2.x, a0);
            a1 = fma2(hd[i][5],  v2.y, a1);
            a0 = fma2(hd[i][6],  v3.x, a0);
            a1 = fma2(hd[i][7],  v3.y, a1);
            a0 = fma2(hd[i][8],  v4.x, a0);
            a1 = fma2(hd[i][9],  v4.y, a1);
            a0 = fma2(hd[i][10], v5.x, a0);
            a1 = fma2(hd[i][11], v5.y, a1);
            a0 = fma2(hd[i][12], v6.x, a0);
            a1 = fma2(hd[i][13], v6.y, a1);
            a0 = fma2(hd[i][14], v7.x, a0);
            a1 = fma2(hd[i][15], v7.y, a1);
            a0 = add2(a0, a1);               // (score_2p, score_2p+1)
            float slo, shi;
            unpack2(slo, shi, a0);
            float smax = fmaxf(slo, shi);
            int   isel = (slo >= shi) ? (2 * p) : (2 * p + 1);
            if (smax > best[i]) { best[i] = smax; bidx[i] = isel; }
        }
    }

#pragma unroll
    for (int i = 0; i < TPT; i++) {
        if (!valid[i]) continue;
        int gidx = kbase + bidx[i];
        unsigned ub = __float_as_uint(best[i]);
        ub = (ub & 0x80000000u) ? ~ub : (ub | 0x80000000u);  // sortable fp32
        u64 key = ((u64)ub << 32) | (unsigned)(0x7FFFFFFF - gidx);
        atomicMax(&g_keys[tok[i]], key);
    }
}

// ---------------------------------------------------------------------------
__global__ void rpq_finalize(float* __restrict__ out, int ntok, int total) {
    int t = blockIdx.x * blockDim.x + threadIdx.x;
    if (t < ntok)
        out[t] = (float)(0x7FFFFFFF - (int)(g_keys[t] & 0xFFFFFFFFull));
    else if (t < total)
        out[t] = 0.f;
}

// ---------------------------------------------------------------------------
extern "C" void kernel_launch(void* const* d_in, const int* in_sizes, int n_in,
                              void* d_out, int out_size) {
    // Bind by element count: hidden (largest), P (smallest), CB (remaining).
    int ih = 0, ip = 0;
    for (int i = 1; i < n_in; i++) {
        if (in_sizes[i] > in_sizes[ih]) ih = i;
        if (in_sizes[i] < in_sizes[ip]) ip = i;
    }
    int ic = 0;
    for (int i = 0; i < n_in; i++)
        if (i != ih && i != ip) ic = i;

    const float* hs = (const float*)d_in[ih];
    const float* P  = (const float*)d_in[ip];
    const float* CB = (const float*)d_in[ic];
    float* out = (float*)d_out;            // float32 labels (R6-proven)

    int ntok   = in_sizes[ih] / IN_DIM;    // 16000
    int kcodes = in_sizes[ic] / E;         // 8192

    rpq_proj<<<(ntok + PTOKB - 1) / PTOKB, PTHREADS>>>(hs, P, ntok);

    dim3 g2((ntok + TOKB - 1) / TOKB, kcodes / CHUNK);   // (63, 16)
    rpq_argmax<<<g2, THREADS>>>(CB, ntok, kcodes);

    rpq_finalize<<<(out_size + 127) / 128, 128>>>(out, ntok, out_size);
}